// round 5
// baseline (speedup 1.0000x reference)
#include <cuda_runtime.h>
#include <math.h>

// Problem constants
#define TS   1024
#define BS   64
#define HID  512
#define G4   2048
#define NCTA 128
#define NGRP 64                        // CTAs per barrier group (one per b-half)
#define LTHREADS 512
#define MROWS 65536                    // T*B rows of the projection GEMM
#define TBH  ((size_t)TS * BS * HID)   // 33554432
#define BH   (BS * HID)                // 32768
// smem: h tile [32][516] + W_hh slice [8 j][stride 2068] (bank-padded)
#define H_STRIDE 516
#define WJ_STRIDE 2068
#define WG_STRIDE 516
#define LSTM_SMEM ((32 * H_STRIDE + 8 * WJ_STRIDE) * 4)   // 132224 bytes

// Scratch (device globals: the sanctioned allocation-free path)
__device__ float g_xgates[(size_t)G4 * MROWS];     // 512 MB, TRANSPOSED [col][row]
__device__ float g_out1[(size_t)TS * BS * HID];    // 128 MB: layer-0 output sequence
__device__ float g_hbuf[2][BH];                    // double-buffered hidden state
__device__ unsigned int g_barG[2];                 // per-group barrier counters

// ---- packed f32x2 helpers (sm_100+ PTX) -----------------------------------
__device__ __forceinline__ unsigned long long fma2(unsigned long long a,
                                                   unsigned long long b,
                                                   unsigned long long c) {
    unsigned long long d;
    asm("fma.rn.f32x2 %0, %1, %2, %3;" : "=l"(d) : "l"(a), "l"(b), "l"(c));
    return d;
}
__device__ __forceinline__ unsigned long long pack2(float x, float y) {
    unsigned long long d;
    asm("mov.b64 %0, {%1, %2};" : "=l"(d) : "f"(x), "f"(y));
    return d;
}
__device__ __forceinline__ float2 unpack2(unsigned long long v) {
    float2 r;
    asm("mov.b64 {%0, %1}, %2;" : "=f"(r.x), "=f"(r.y) : "l"(v));
    return r;
}

// ---- release/acquire barrier primitives (no MEMBAR.GL on critical path) ----
__device__ __forceinline__ void red_release_add(unsigned int* p, unsigned int v) {
    asm volatile("red.release.gpu.global.add.u32 [%0], %1;" :: "l"(p), "r"(v) : "memory");
}
__device__ __forceinline__ unsigned int ld_acquire(const unsigned int* p) {
    unsigned int v;
    asm volatile("ld.acquire.gpu.global.u32 %0, [%1];" : "=r"(v) : "l"(p) : "memory");
    return v;
}

// ---------------------------------------------------------------------------
// Input projection GEMM: C_T[g][m] = sum_k A[m,k] * W[g,k] + b1[g] + b2[g]
// Tile 128x128x16, 256 threads, 8x8 per thread, FFMA2 inner product.
// Output stored TRANSPOSED so the recurrence reads coalesced in batch.
// Also resets the recurrence barrier counters (runs before each lstm pass).
// ---------------------------------------------------------------------------
__global__ __launch_bounds__(256, 2) void gemm_xg(
    const float* __restrict__ A,
    const float* __restrict__ W,
    const float* __restrict__ b1,
    const float* __restrict__ b2)
{
    if (blockIdx.x == 0 && blockIdx.y == 0 && threadIdx.x == 0) {
        g_barG[0] = 0u;
        g_barG[1] = 0u;
    }

    __shared__ float As[16][128];
    __shared__ float Bs[16][128];
    const int tid = threadIdx.x;
    const int m0 = blockIdx.y * 128;
    const int n0 = blockIdx.x * 128;
    const int tx = tid & 15, ty = tid >> 4;
    const int lr = tid >> 2;
    const int lk = (tid & 3) << 2;

    const float* Ap = A + (size_t)(m0 + lr) * HID + lk;
    const float* Wp = W + (size_t)(n0 + lr) * HID + lk;

    unsigned long long acc2[8][4];
#pragma unroll
    for (int i = 0; i < 8; i++)
#pragma unroll
        for (int j = 0; j < 4; j++) acc2[i][j] = 0ull;

    for (int k0 = 0; k0 < HID; k0 += 16) {
        float4 a0 = *(const float4*)(Ap + k0);
        float4 a1 = *(const float4*)(Ap + (size_t)64 * HID + k0);
        float4 w0 = *(const float4*)(Wp + k0);
        float4 w1 = *(const float4*)(Wp + (size_t)64 * HID + k0);
        __syncthreads();
        As[lk + 0][lr] = a0.x; As[lk + 1][lr] = a0.y; As[lk + 2][lr] = a0.z; As[lk + 3][lr] = a0.w;
        As[lk + 0][lr + 64] = a1.x; As[lk + 1][lr + 64] = a1.y; As[lk + 2][lr + 64] = a1.z; As[lk + 3][lr + 64] = a1.w;
        Bs[lk + 0][lr] = w0.x; Bs[lk + 1][lr] = w0.y; Bs[lk + 2][lr] = w0.z; Bs[lk + 3][lr] = w0.w;
        Bs[lk + 0][lr + 64] = w1.x; Bs[lk + 1][lr + 64] = w1.y; Bs[lk + 2][lr + 64] = w1.z; Bs[lk + 3][lr + 64] = w1.w;
        __syncthreads();
#pragma unroll
        for (int k = 0; k < 16; k++) {
            float a[8];
            *(float4*)&a[0] = *(const float4*)&As[k][ty * 8];
            *(float4*)&a[4] = *(const float4*)&As[k][ty * 8 + 4];
            const ulonglong2* bp = (const ulonglong2*)&Bs[k][tx * 8];
            ulonglong2 t0 = bp[0];
            ulonglong2 t1 = bp[1];
#pragma unroll
            for (int i = 0; i < 8; i++) {
                unsigned long long ad = pack2(a[i], a[i]);
                acc2[i][0] = fma2(ad, t0.x, acc2[i][0]);
                acc2[i][1] = fma2(ad, t0.y, acc2[i][1]);
                acc2[i][2] = fma2(ad, t1.x, acc2[i][2]);
                acc2[i][3] = fma2(ad, t1.y, acc2[i][3]);
            }
        }
    }

    float val[8][8];
#pragma unroll
    for (int i = 0; i < 8; i++)
#pragma unroll
        for (int jp = 0; jp < 4; jp++) {
            float2 p = unpack2(acc2[i][jp]);
            val[i][2 * jp] = p.x;
            val[i][2 * jp + 1] = p.y;
        }
#pragma unroll
    for (int u = 0; u < 8; u++) {
        int col = n0 + tx * 8 + u;
        float bias = b1[col] + b2[col];
        float* Cp = g_xgates + (size_t)col * MROWS + m0 + ty * 8;
        float4 lo, hi;
        lo.x = val[0][u] + bias; lo.y = val[1][u] + bias;
        lo.z = val[2][u] + bias; lo.w = val[3][u] + bias;
        hi.x = val[4][u] + bias; hi.y = val[5][u] + bias;
        hi.z = val[6][u] + bias; hi.w = val[7][u] + bias;
        *(float4*)Cp = lo;
        *(float4*)(Cp + 4) = hi;
    }
}

// ---------------------------------------------------------------------------
// Persistent recurrence. 128 CTAs x 512 threads (k-split: 2 threads per cell,
// interleaved 16B k-chunks, combined with one shfl.bfly per gate).
// 16 warps/SM = 4/SMSP for latency hiding. W_hh in smem (loaded once),
// c in register. Two-group release/acquire grid barrier per step.
// ---------------------------------------------------------------------------
__device__ __forceinline__ float sigmoidf_(float x) { return 1.f / (1.f + expf(-x)); }

__global__ __launch_bounds__(LTHREADS, 1) void lstm_kernel(
    const float* __restrict__ Whh,   // [4H][H] for this layer
    const float* __restrict__ h0,    // [B][H]
    const float* __restrict__ c0,    // [B][H]
    const float* __restrict__ xg,    // transposed gates [4H][T*B]
    float* __restrict__ out,         // [T][B][H]
    float* __restrict__ hn,          // [B][H]
    float* __restrict__ cn)          // [B][H]
{
    extern __shared__ float sm[];
    float* h_sm = sm;                        // [32][516]
    float* w_sm = sm + 32 * H_STRIDE;        // [8 j][4 g x 516] stride 2068

    const int tid  = threadIdx.x;
    const int cta  = blockIdx.x;
    const int jb   = cta & 63;       // 64 j-blocks of 8
    const int bb   = cta >> 6;       // 2 b-blocks of 32 -> barrier group
    const int warp = tid >> 5;
    const int lane = tid & 31;
    const int bq   = warp & 3;       // warp b-quad (0..3)
    const int jq   = warp >> 2;      // warp j-pair (0..3)
    const int bo   = lane & 7;       // lane b offset
    const int jp   = (lane >> 3) & 1;// lane j within pair
    const int kh   = lane >> 4;      // lane k-half (0/1) -> bfly 16 partner
    const int bl   = bq * 8 + bo;    // b_local 0..31
    const int jl   = jq * 2 + jp;    // j_local 0..7
    const int j    = jb * 8 + jl;
    const int b    = bb * 32 + bl;
    const int bj   = b * HID + j;

    unsigned int* bar = &g_barG[bb];

    // preload this CTA's W_hh slice: w_sm[jl][g][k], strides bank-padded
    {
        const float4* Wsrc = (const float4*)Whh;
#pragma unroll
        for (int idx = tid; idx < 4096; idx += LTHREADS) {   // float4 units
            int wjl = idx >> 9;
            int rem = idx & 511;
            int g   = rem >> 7;
            int k4  = rem & 127;
            *(float4*)&w_sm[wjl * WJ_STRIDE + g * WG_STRIDE + k4 * 4] =
                Wsrc[(((size_t)(g * HID + jb * 8 + wjl)) * HID >> 2) + k4];
        }
    }

    float c = c0[bj];
    if (kh == 0) __stcg(&g_hbuf[0][bj], h0[bj]);

    // per-gate xg base pointers (transposed layout: coalesced lane->b)
    const float* xi  = xg + (size_t)(0 * HID + j) * MROWS + b;
    const float* xf  = xg + (size_t)(1 * HID + j) * MROWS + b;
    const float* xgp = xg + (size_t)(2 * HID + j) * MROWS + b;
    const float* xo  = xg + (size_t)(3 * HID + j) * MROWS + b;

    // k-chunk interleave: thread kh handles chunks {2i + kh}, i = 0..63
    const ulonglong2* hp = (const ulonglong2*)&h_sm[bl * H_STRIDE] + kh;
    const ulonglong2* W0 = (const ulonglong2*)&w_sm[jl * WJ_STRIDE + 0 * WG_STRIDE] + kh;
    const ulonglong2* W1 = (const ulonglong2*)&w_sm[jl * WJ_STRIDE + 1 * WG_STRIDE] + kh;
    const ulonglong2* W2 = (const ulonglong2*)&w_sm[jl * WJ_STRIDE + 2 * WG_STRIDE] + kh;
    const ulonglong2* W3 = (const ulonglong2*)&w_sm[jl * WJ_STRIDE + 3 * WG_STRIDE] + kh;

    // initial barrier: h0 writes of this group visible before step 0
    unsigned expect = 0;
    __syncthreads();
    if (tid == 0) {
        red_release_add(bar, 1u);
        expect += NGRP;
        while (ld_acquire(bar) < expect) { }
    }
    __syncthreads();

    // prefetch step-0 gate biases
    float vxi = __ldg(xi), vxf = __ldg(xf), vxg = __ldg(xgp), vxo = __ldg(xo);

    float h = 0.f;
    for (int t = 0; t < TS; t++) {
        const float* hcur = g_hbuf[t & 1];
        // stage this group's 32-batch h slice into smem (L2, coalesced)
#pragma unroll
        for (int idx = tid; idx < 32 * 128; idx += LTHREADS) {
            int r  = idx >> 7;
            int c4 = idx & 127;
            float4 v = __ldcg((const float4*)(hcur + (size_t)(bb * 32 + r) * HID) + c4);
            *(float4*)&h_sm[r * H_STRIDE + c4 * 4] = v;
        }
        __syncthreads();

        unsigned long long ai2 = 0ull, af2 = 0ull, ag2 = 0ull, ao2 = 0ull;
#pragma unroll 8
        for (int i = 0; i < 64; i++) {
            ulonglong2 hv = hp[2 * i];
            ulonglong2 w0 = W0[2 * i], w1 = W1[2 * i], w2 = W2[2 * i], w3 = W3[2 * i];
            ai2 = fma2(hv.x, w0.x, ai2); ai2 = fma2(hv.y, w0.y, ai2);
            af2 = fma2(hv.x, w1.x, af2); af2 = fma2(hv.y, w1.y, af2);
            ag2 = fma2(hv.x, w2.x, ag2); ag2 = fma2(hv.y, w2.y, ag2);
            ao2 = fma2(hv.x, w3.x, ao2); ao2 = fma2(hv.y, w3.y, ao2);
        }

        float2 pi = unpack2(ai2); float2 pf = unpack2(af2);
        float2 pg = unpack2(ag2); float2 po = unpack2(ao2);
        float ri = pi.x + pi.y, rf = pf.x + pf.y;
        float rg = pg.x + pg.y, ro = po.x + po.y;
        // combine the two k-halves (partner lane = lane ^ 16)
        ri += __shfl_xor_sync(0xffffffffu, ri, 16);
        rf += __shfl_xor_sync(0xffffffffu, rf, 16);
        rg += __shfl_xor_sync(0xffffffffu, rg, 16);
        ro += __shfl_xor_sync(0xffffffffu, ro, 16);

        float ig = sigmoidf_(ri + vxi);
        float fg = sigmoidf_(rf + vxf);
        float gg = tanhf(rg + vxg);
        float og = sigmoidf_(ro + vxo);
        c = fg * c + ig * gg;
        h = og * tanhf(c);

        // publish h for step t+1, then arrive (release orders the stcg)
        if (kh == 0) __stcg(&g_hbuf[(t + 1) & 1][bj], h);
        __syncthreads();
        if (tid == 0) {
            red_release_add(bar, 1u);
            expect += NGRP;
        }

        // overlap with barrier wait: out[] DRAM store + next-step xg prefetch
        if (kh == 0) out[((size_t)t * BS + b) * HID + j] = h;
        if (t + 1 < TS) {
            int toff = (t + 1) * BS;
            vxi = __ldg(xi + toff);
            vxf = __ldg(xf + toff);
            vxg = __ldg(xgp + toff);
            vxo = __ldg(xo + toff);
        }

        if (tid == 0) {
            while (ld_acquire(bar) < expect) { }
        }
        __syncthreads();
    }

    if (kh == 0) {
        hn[bj] = h;
        cn[bj] = c;
    }
}

// ---------------------------------------------------------------------------
// Launch: per layer {gemm (resets barrier) -> persistent recurrence}.
// Output layout: [layer_out (T,B,H)][h_n (L,B,H)][c_n (L,B,H)]
// ---------------------------------------------------------------------------
extern "C" void kernel_launch(void* const* d_in, const int* in_sizes, int n_in,
                              void* d_out, int out_size)
{
    const float* x    = (const float*)d_in[0];
    const float* h0   = (const float*)d_in[1];
    const float* c0   = (const float*)d_in[2];
    const float* W_ih = (const float*)d_in[3];
    const float* W_hh = (const float*)d_in[4];
    const float* b_ih = (const float*)d_in[5];
    const float* b_hh = (const float*)d_in[6];
    float* out = (float*)d_out;

    cudaFuncSetAttribute(lstm_kernel, cudaFuncAttributeMaxDynamicSharedMemorySize, LSTM_SMEM);

    void* p_out1_v = nullptr;
    cudaGetSymbolAddress(&p_out1_v, g_out1);
    float* p_out1 = (float*)p_out1_v;
    void* p_xg_v = nullptr;
    cudaGetSymbolAddress(&p_xg_v, g_xgates);
    const float* p_xg = (const float*)p_xg_v;

    dim3 ggrid(G4 / 128, MROWS / 128);   // (16, 512)

    // Layer 0
    gemm_xg<<<ggrid, 256>>>(x, W_ih, b_ih, b_hh);
    lstm_kernel<<<NCTA, LTHREADS, LSTM_SMEM>>>(
        W_hh, h0, c0, p_xg,
        p_out1,
        out + TBH,                       // h_n[0]
        out + TBH + 2 * (size_t)BH);     // c_n[0]

    // Layer 1
    gemm_xg<<<ggrid, 256>>>(p_out1, W_ih + (size_t)G4 * HID, b_ih + G4, b_hh + G4);
    lstm_kernel<<<NCTA, LTHREADS, LSTM_SMEM>>>(
        W_hh + (size_t)G4 * HID, h0 + BH, c0 + BH, p_xg,
        out,                             // final layer_out
        out + TBH + (size_t)BH,          // h_n[1]
        out + TBH + 3 * (size_t)BH);     // c_n[1]

    (void)in_sizes; (void)n_in; (void)out_size;
}